// round 4
// baseline (speedup 1.0000x reference)
#include <cuda_runtime.h>
#include <math.h>
#include <stdint.h>

// FullAttention B=4, L=S=2048, H=8, E=D=64, fp32 in/out.
// Flash-attention, tensor cores via mma.sync.m16n8k8 tf32.
// CTA = 128 threads (4 warps), Q tile 64 rows (16 per warp), KV chunk 64.

#define BM 64
#define BN 64
#define LDQ 68   // Q/K/P stride: A/B-frag pattern bank = 4*(l/4)+(l%4) -> conflict-free
#define LDK 68
#define LDV 72   // V stride: B-frag pattern bank = 8*(l%4)+(l/4) -> conflict-free
#define LDPD 68

static constexpr int Bb = 4, Ll = 2048, Ss = 2048, Hh = 8, Ee = 64, Dd = 64;

__device__ __forceinline__ uint32_t f2tf32(float f) {
    uint32_t u;
    asm("cvt.rna.tf32.f32 %0, %1;" : "=r"(u) : "f"(f));
    return u;
}

__device__ __forceinline__ void mma_tf32(float* c,
                                         uint32_t a0, uint32_t a1, uint32_t a2, uint32_t a3,
                                         uint32_t b0, uint32_t b1) {
    asm volatile(
        "mma.sync.aligned.m16n8k8.row.col.f32.tf32.tf32.f32 "
        "{%0,%1,%2,%3}, {%4,%5,%6,%7}, {%8,%9}, {%0,%1,%2,%3};"
        : "+f"(c[0]), "+f"(c[1]), "+f"(c[2]), "+f"(c[3])
        : "r"(a0), "r"(a1), "r"(a2), "r"(a3), "r"(b0), "r"(b1));
}

__global__ __launch_bounds__(128, 3)
void flash_tf32(const float* __restrict__ Q, const float* __restrict__ K,
                const float* __restrict__ V, float* __restrict__ Out)
{
    extern __shared__ uint32_t smem[];
    uint32_t* sQ = smem;                  // [BM][LDQ]  tf32 bits (pre-scaled)
    uint32_t* sK = sQ + BM * LDQ;         // [BN][LDK]
    uint32_t* sV = sK + BN * LDK;         // [BN][LDV]
    uint32_t* sP = sV + BN * LDV;         // [BM][LDPD]

    const int tid  = threadIdx.x;
    const int lane = tid & 31;
    const int warp = tid >> 5;
    const int ty4  = lane >> 2;   // 0..7
    const int tx4  = lane & 3;    // 0..3
    const int mbase = warp * 16;  // warp's Q-row base within tile

    const int qtile = blockIdx.x, h = blockIdx.y, b = blockIdx.z;
    const int q0 = qtile * BM;
    const int gstride = Hh * Ee;  // 512 floats between consecutive l/s

    const float* Qbase = Q + ((size_t)(b * Ll + q0) * Hh + h) * Ee;
    const float* Kbase = K + ((size_t)b * Ss * Hh + h) * Ee;
    const float* Vbase = V + ((size_t)b * Ss * Hh + h) * Dd;

    const float scale = 0.125f;  // 1/sqrt(64), folded into Q

    // ---- Load Q tile (scaled, tf32-rounded). 1024 float4, 128 threads, 8 iters.
    #pragma unroll
    for (int it = 0; it < 8; it++) {
        int idx = it * 128 + tid;
        int row = idx >> 4, c4 = idx & 15;
        float4 v = *reinterpret_cast<const float4*>(Qbase + (size_t)row * gstride + c4 * 4);
        uint4 w;
        w.x = f2tf32(v.x * scale); w.y = f2tf32(v.y * scale);
        w.z = f2tf32(v.z * scale); w.w = f2tf32(v.w * scale);
        *reinterpret_cast<uint4*>(&sQ[row * LDQ + c4 * 4]) = w;
    }

    // O accumulators: 8 d-tiles x 4 (C-frag). Rows: ty4 and ty4+8.
    float acc_o[8][4];
    float m_run[2] = {-INFINITY, -INFINITY};
    float l_run[2] = {0.f, 0.f};
    #pragma unroll
    for (int n = 0; n < 8; n++)
        #pragma unroll
        for (int j = 0; j < 4; j++) acc_o[n][j] = 0.f;

    for (int s0 = 0; s0 < Ss; s0 += BN) {
        __syncthreads();  // prior iteration's reads of sK/sV/sP done

        // ---- Load K,V chunk (tf32-rounded)
        #pragma unroll
        for (int it = 0; it < 8; it++) {
            int idx = it * 128 + tid;
            int row = idx >> 4, c4 = idx & 15;
            float4 kv = *reinterpret_cast<const float4*>(Kbase + (size_t)(s0 + row) * gstride + c4 * 4);
            uint4 kw;
            kw.x = f2tf32(kv.x); kw.y = f2tf32(kv.y); kw.z = f2tf32(kv.z); kw.w = f2tf32(kv.w);
            *reinterpret_cast<uint4*>(&sK[row * LDK + c4 * 4]) = kw;
            float4 vv = *reinterpret_cast<const float4*>(Vbase + (size_t)(s0 + row) * gstride + c4 * 4);
            uint4 vw;
            vw.x = f2tf32(vv.x); vw.y = f2tf32(vv.y); vw.z = f2tf32(vv.z); vw.w = f2tf32(vv.w);
            *reinterpret_cast<uint4*>(&sV[row * LDV + c4 * 4]) = vw;
        }
        __syncthreads();

        // ---- S = Q @ K^T : 8 k-steps x 8 n-tiles of m16n8k8
        float acc[8][4];
        #pragma unroll
        for (int n = 0; n < 8; n++)
            #pragma unroll
            for (int j = 0; j < 4; j++) acc[n][j] = 0.f;

        #pragma unroll
        for (int ks = 0; ks < 8; ks++) {
            const int k0 = ks * 8;
            uint32_t a0 = sQ[(mbase + ty4)     * LDQ + k0 + tx4];
            uint32_t a1 = sQ[(mbase + ty4 + 8) * LDQ + k0 + tx4];
            uint32_t a2 = sQ[(mbase + ty4)     * LDQ + k0 + tx4 + 4];
            uint32_t a3 = sQ[(mbase + ty4 + 8) * LDQ + k0 + tx4 + 4];
            #pragma unroll
            for (int n = 0; n < 8; n++) {
                uint32_t b0 = sK[(n * 8 + ty4) * LDK + k0 + tx4];       // B[k][n]=K[n][k]
                uint32_t b1 = sK[(n * 8 + ty4) * LDK + k0 + tx4 + 4];
                mma_tf32(acc[n], a0, a1, a2, a3, b0, b1);
            }
        }

        // ---- Online softmax. Thread owns rows (ty4, ty4+8); quad (xor 1,2) spans each row.
        float mx0 = -INFINITY, mx1 = -INFINITY;
        #pragma unroll
        for (int n = 0; n < 8; n++) {
            mx0 = fmaxf(mx0, fmaxf(acc[n][0], acc[n][1]));
            mx1 = fmaxf(mx1, fmaxf(acc[n][2], acc[n][3]));
        }
        mx0 = fmaxf(mx0, __shfl_xor_sync(0xffffffffu, mx0, 1));
        mx0 = fmaxf(mx0, __shfl_xor_sync(0xffffffffu, mx0, 2));
        mx1 = fmaxf(mx1, __shfl_xor_sync(0xffffffffu, mx1, 1));
        mx1 = fmaxf(mx1, __shfl_xor_sync(0xffffffffu, mx1, 2));

        const float mn0 = fmaxf(m_run[0], mx0);
        const float mn1 = fmaxf(m_run[1], mx1);
        const float al0 = __expf(m_run[0] - mn0);   // 0 on first tile
        const float al1 = __expf(m_run[1] - mn1);

        float sum0 = 0.f, sum1 = 0.f;
        #pragma unroll
        for (int n = 0; n < 8; n++) {
            float p0 = __expf(acc[n][0] - mn0);
            float p1 = __expf(acc[n][1] - mn0);
            float p2 = __expf(acc[n][2] - mn1);
            float p3 = __expf(acc[n][3] - mn1);
            sum0 += p0 + p1;
            sum1 += p2 + p3;
            uint2 lo; lo.x = f2tf32(p0); lo.y = f2tf32(p1);
            *reinterpret_cast<uint2*>(&sP[(mbase + ty4)     * LDPD + n * 8 + 2 * tx4]) = lo;
            uint2 hi; hi.x = f2tf32(p2); hi.y = f2tf32(p3);
            *reinterpret_cast<uint2*>(&sP[(mbase + ty4 + 8) * LDPD + n * 8 + 2 * tx4]) = hi;
        }
        sum0 += __shfl_xor_sync(0xffffffffu, sum0, 1);
        sum0 += __shfl_xor_sync(0xffffffffu, sum0, 2);
        sum1 += __shfl_xor_sync(0xffffffffu, sum1, 1);
        sum1 += __shfl_xor_sync(0xffffffffu, sum1, 2);

        l_run[0] = l_run[0] * al0 + sum0;  m_run[0] = mn0;
        l_run[1] = l_run[1] * al1 + sum1;  m_run[1] = mn1;

        #pragma unroll
        for (int n = 0; n < 8; n++) {
            acc_o[n][0] *= al0;  acc_o[n][1] *= al0;
            acc_o[n][2] *= al1;  acc_o[n][3] *= al1;
        }
        __syncwarp();  // P visible across the warp (own 16 rows only)

        // ---- O += P @ V : 8 k-steps x 8 d-tiles
        #pragma unroll
        for (int ks = 0; ks < 8; ks++) {
            const int k0 = ks * 8;
            uint32_t a0 = sP[(mbase + ty4)     * LDPD + k0 + tx4];
            uint32_t a1 = sP[(mbase + ty4 + 8) * LDPD + k0 + tx4];
            uint32_t a2 = sP[(mbase + ty4)     * LDPD + k0 + tx4 + 4];
            uint32_t a3 = sP[(mbase + ty4 + 8) * LDPD + k0 + tx4 + 4];
            #pragma unroll
            for (int n = 0; n < 8; n++) {
                uint32_t b0 = sV[(k0 + tx4)     * LDV + n * 8 + ty4];   // B[k][n]=V[k][n]
                uint32_t b1 = sV[(k0 + tx4 + 4) * LDV + n * 8 + ty4];
                mma_tf32(acc_o[n], a0, a1, a2, a3, b0, b1);
            }
        }
    }

    // ---- Epilogue: normalize, write Out[b, q0+row, h, d]
    const float inv0 = 1.f / l_run[0];
    const float inv1 = 1.f / l_run[1];
    const int r0 = q0 + mbase + ty4;
    const int r1 = r0 + 8;
    float* O0 = Out + ((size_t)(b * Ll + r0) * Hh + h) * Dd;
    float* O1 = Out + ((size_t)(b * Ll + r1) * Hh + h) * Dd;
    #pragma unroll
    for (int n = 0; n < 8; n++) {
        const int col = n * 8 + 2 * tx4;
        float2 v0; v0.x = acc_o[n][0] * inv0; v0.y = acc_o[n][1] * inv0;
        *reinterpret_cast<float2*>(O0 + col) = v0;
        float2 v1; v1.x = acc_o[n][2] * inv1; v1.y = acc_o[n][3] * inv1;
        *reinterpret_cast<float2*>(O1 + col) = v1;
    }
}

extern "C" void kernel_launch(void* const* d_in, const int* in_sizes, int n_in,
                              void* d_out, int out_size)
{
    const float* Q = (const float*)d_in[0];
    const float* K = (const float*)d_in[1];
    const float* V = (const float*)d_in[2];
    float* Out = (float*)d_out;

    const int smem_bytes = (BM * LDQ + BN * LDK + BN * LDV + BM * LDPD) * 4;  // 70656
    cudaFuncSetAttribute(flash_tf32,
                         cudaFuncAttributeMaxDynamicSharedMemorySize, smem_bytes);

    dim3 grid(Ll / BM, Hh, Bb);   // (32, 8, 4); x-fastest keeps same-(b,h) CTAs adjacent for L2 K/V reuse
    flash_tf32<<<grid, 128, smem_bytes>>>(Q, K, V, Out);
}

// round 6
// speedup vs baseline: 1.0806x; 1.0806x over previous
#include <cuda_runtime.h>
#include <cuda_fp16.h>
#include <math.h>
#include <stdint.h>

// FullAttention B=4, L=S=2048, H=8, E=D=64, fp32 in/out.
// Flash attention with mma.sync.m16n8k16 fp16 (fp32 accum).
// CTA = 128 threads (4 warps), Q tile 64 rows (16/warp), KV chunk 64.
// fp16 mantissa == tf32 mantissa -> same accuracy as tf32, 2x tensor rate,
// 2x smem-crossbar efficiency. V staged transposed so PV B-frags are
// contiguous half2 loads. All smem strides = 72 halfs -> every fragment
// access pattern hits 32 distinct banks.

#define BM 64
#define BN 64
#define LDH 72   // half-element stride; (row*72*2 + 2*col)/4 % 32 = 4*ty4+tx4 pattern

static constexpr int Bb = 4, Ll = 2048, Ss = 2048, Hh = 8, Ee = 64, Dd = 64;

__device__ __forceinline__ void mma_fp16(float* c, uint32_t a0, uint32_t a1,
                                         uint32_t a2, uint32_t a3,
                                         uint32_t b0, uint32_t b1) {
    asm volatile(
        "mma.sync.aligned.m16n8k16.row.col.f32.f16.f16.f32 "
        "{%0,%1,%2,%3}, {%4,%5,%6,%7}, {%8,%9}, {%0,%1,%2,%3};"
        : "+f"(c[0]), "+f"(c[1]), "+f"(c[2]), "+f"(c[3])
        : "r"(a0), "r"(a1), "r"(a2), "r"(a3), "r"(b0), "r"(b1));
}
__device__ __forceinline__ uint32_t h2u(__half2 h) { return *reinterpret_cast<uint32_t*>(&h); }

__global__ __launch_bounds__(128, 3)
void flash_fp16(const float* __restrict__ Q, const float* __restrict__ K,
                const float* __restrict__ V, float* __restrict__ Out)
{
    __shared__ __align__(16) __half sQ[BM * LDH];
    __shared__ __align__(16) __half sK[BN * LDH];
    __shared__ __align__(16) __half sVt[Dd * LDH];   // transposed: [d][s]
    __shared__ __align__(16) __half sP[BM * LDH];

    const int tid  = threadIdx.x;
    const int lane = tid & 31;
    const int warp = tid >> 5;
    const int ty4  = lane >> 2;    // 0..7
    const int tx4  = lane & 3;     // 0..3
    const int mbase = warp * 16;

    const int qtile = blockIdx.x, h = blockIdx.y, b = blockIdx.z;
    const int q0 = qtile * BM;
    const int gs = Hh * Ee;        // 512 floats between consecutive l/s

    const float* Qb = Q + ((size_t)(b * Ll + q0) * Hh + h) * Ee;
    const float* Kb = K + ((size_t)b * Ss * Hh + h) * Ee;
    const float* Vb = V + ((size_t)b * Ss * Hh + h) * Dd;

    const float scale = 0.125f;    // 1/sqrt(64), folded into Q

    // ---- Load Q (scaled -> fp16). 1024 float4-groups, 128 thr, 8 iters.
    #pragma unroll
    for (int it = 0; it < 8; it++) {
        int idx = it * 128 + tid;
        int row = idx >> 4, c4 = idx & 15;
        float4 v = *reinterpret_cast<const float4*>(Qb + (size_t)row * gs + c4 * 4);
        uint2 w;
        w.x = h2u(__floats2half2_rn(v.x * scale, v.y * scale));
        w.y = h2u(__floats2half2_rn(v.z * scale, v.w * scale));
        *reinterpret_cast<uint2*>(&sQ[row * LDH + c4 * 4]) = w;
    }

    float acc_o[8][4];
    float m_run[2] = {-INFINITY, -INFINITY};
    float l_run[2] = {0.f, 0.f};
    #pragma unroll
    for (int n = 0; n < 8; n++)
        #pragma unroll
        for (int j = 0; j < 4; j++) acc_o[n][j] = 0.f;

    for (int s0 = 0; s0 < Ss; s0 += BN) {
        __syncthreads();   // prior tile's reads of sK/sVt done

        // ---- Stage K (row-major) and V (transposed) as fp16
        #pragma unroll
        for (int it = 0; it < 8; it++) {
            int idx = it * 128 + tid;
            int row = idx >> 4, c4 = idx & 15;
            float4 kv = *reinterpret_cast<const float4*>(Kb + (size_t)(s0 + row) * gs + c4 * 4);
            uint2 kw;
            kw.x = h2u(__floats2half2_rn(kv.x, kv.y));
            kw.y = h2u(__floats2half2_rn(kv.z, kv.w));
            *reinterpret_cast<uint2*>(&sK[row * LDH + c4 * 4]) = kw;
            float4 vv = *reinterpret_cast<const float4*>(Vb + (size_t)(s0 + row) * gs + c4 * 4);
            sVt[(c4 * 4 + 0) * LDH + row] = __float2half_rn(vv.x);
            sVt[(c4 * 4 + 1) * LDH + row] = __float2half_rn(vv.y);
            sVt[(c4 * 4 + 2) * LDH + row] = __float2half_rn(vv.z);
            sVt[(c4 * 4 + 3) * LDH + row] = __float2half_rn(vv.w);
        }
        __syncthreads();

        // ---- S = Q @ K^T : 4 k16-steps x 8 n-tiles
        float acc[8][4];
        #pragma unroll
        for (int n = 0; n < 8; n++)
            #pragma unroll
            for (int j = 0; j < 4; j++) acc[n][j] = 0.f;

        #pragma unroll
        for (int ks = 0; ks < 4; ks++) {
            const int k0 = ks * 16;
            uint32_t a0 = *reinterpret_cast<uint32_t*>(&sQ[(mbase + ty4)     * LDH + k0 + 2 * tx4]);
            uint32_t a1 = *reinterpret_cast<uint32_t*>(&sQ[(mbase + ty4 + 8) * LDH + k0 + 2 * tx4]);
            uint32_t a2 = *reinterpret_cast<uint32_t*>(&sQ[(mbase + ty4)     * LDH + k0 + 2 * tx4 + 8]);
            uint32_t a3 = *reinterpret_cast<uint32_t*>(&sQ[(mbase + ty4 + 8) * LDH + k0 + 2 * tx4 + 8]);
            #pragma unroll
            for (int n = 0; n < 8; n++) {
                uint32_t b0 = *reinterpret_cast<uint32_t*>(&sK[(n * 8 + ty4) * LDH + k0 + 2 * tx4]);
                uint32_t b1 = *reinterpret_cast<uint32_t*>(&sK[(n * 8 + ty4) * LDH + k0 + 2 * tx4 + 8]);
                mma_fp16(acc[n], a0, a1, a2, a3, b0, b1);
            }
        }

        // ---- Online softmax (rows ty4, ty4+8; quad xor 1,2 spans a row)
        float mx0 = -INFINITY, mx1 = -INFINITY;
        #pragma unroll
        for (int n = 0; n < 8; n++) {
            mx0 = fmaxf(mx0, fmaxf(acc[n][0], acc[n][1]));
            mx1 = fmaxf(mx1, fmaxf(acc[n][2], acc[n][3]));
        }
        mx0 = fmaxf(mx0, __shfl_xor_sync(0xffffffffu, mx0, 1));
        mx0 = fmaxf(mx0, __shfl_xor_sync(0xffffffffu, mx0, 2));
        mx1 = fmaxf(mx1, __shfl_xor_sync(0xffffffffu, mx1, 1));
        mx1 = fmaxf(mx1, __shfl_xor_sync(0xffffffffu, mx1, 2));

        const float mn0 = fmaxf(m_run[0], mx0);
        const float mn1 = fmaxf(m_run[1], mx1);
        const float al0 = __expf(m_run[0] - mn0);
        const float al1 = __expf(m_run[1] - mn1);

        float sum0 = 0.f, sum1 = 0.f;
        #pragma unroll
        for (int n = 0; n < 8; n++) {
            float p0 = __expf(acc[n][0] - mn0);
            float p1 = __expf(acc[n][1] - mn0);
            float p2 = __expf(acc[n][2] - mn1);
            float p3 = __expf(acc[n][3] - mn1);
            sum0 += p0 + p1;
            sum1 += p2 + p3;
            *reinterpret_cast<uint32_t*>(&sP[(mbase + ty4)     * LDH + n * 8 + 2 * tx4]) =
                h2u(__floats2half2_rn(p0, p1));
            *reinterpret_cast<uint32_t*>(&sP[(mbase + ty4 + 8) * LDH + n * 8 + 2 * tx4]) =
                h2u(__floats2half2_rn(p2, p3));
        }
        sum0 += __shfl_xor_sync(0xffffffffu, sum0, 1);
        sum0 += __shfl_xor_sync(0xffffffffu, sum0, 2);
        sum1 += __shfl_xor_sync(0xffffffffu, sum1, 1);
        sum1 += __shfl_xor_sync(0xffffffffu, sum1, 2);

        l_run[0] = l_run[0] * al0 + sum0;  m_run[0] = mn0;
        l_run[1] = l_run[1] * al1 + sum1;  m_run[1] = mn1;

        #pragma unroll
        for (int n = 0; n < 8; n++) {
            acc_o[n][0] *= al0;  acc_o[n][1] *= al0;
            acc_o[n][2] *= al1;  acc_o[n][3] *= al1;
        }
        __syncwarp();   // sP rows are warp-private

        // ---- O += P @ V : 4 k16-steps x 8 d-tiles (B from transposed V)
        #pragma unroll
        for (int ks = 0; ks < 4; ks++) {
            const int k0 = ks * 16;
            uint32_t a0 = *reinterpret_cast<uint32_t*>(&sP[(mbase + ty4)     * LDH + k0 + 2 * tx4]);
            uint32_t a1 = *reinterpret_cast<uint32_t*>(&sP[(mbase + ty4 + 8) * LDH + k0 + 2 * tx4]);
            uint32_t a2 = *reinterpret_cast<uint32_t*>(&sP[(mbase + ty4)     * LDH + k0 + 2 * tx4 + 8]);
            uint32_t a3 = *reinterpret_cast<uint32_t*>(&sP[(mbase + ty4 + 8) * LDH + k0 + 2 * tx4 + 8]);
            #pragma unroll
            for (int n = 0; n < 8; n++) {
                uint32_t b0 = *reinterpret_cast<uint32_t*>(&sVt[(n * 8 + ty4) * LDH + k0 + 2 * tx4]);
                uint32_t b1 = *reinterpret_cast<uint32_t*>(&sVt[(n * 8 + ty4) * LDH + k0 + 2 * tx4 + 8]);
                mma_fp16(acc_o[n], a0, a1, a2, a3, b0, b1);
            }
        }
    }

    // ---- Epilogue
    const float inv0 = 1.f / l_run[0];
    const float inv1 = 1.f / l_run[1];
    const int r0 = q0 + mbase + ty4;
    float* O0 = Out + ((size_t)(b * Ll + r0)     * Hh + h) * Dd;
    float* O1 = Out + ((size_t)(b * Ll + r0 + 8) * Hh + h) * Dd;
    #pragma unroll
    for (int n = 0; n < 8; n++) {
        const int col = n * 8 + 2 * tx4;
        float2 v0; v0.x = acc_o[n][0] * inv0; v0.y = acc_o[n][1] * inv0;
        *reinterpret_cast<float2*>(O0 + col) = v0;
        float2 v1; v1.x = acc_o[n][2] * inv1; v1.y = acc_o[n][3] * inv1;
        *reinterpret_cast<float2*>(O1 + col) = v1;
    }
}

extern "C" void kernel_launch(void* const* d_in, const int* in_sizes, int n_in,
                              void* d_out, int out_size)
{
    const float* Q = (const float*)d_in[0];
    const float* K = (const float*)d_in[1];
    const float* V = (const float*)d_in[2];
    float* Out = (float*)d_out;

    dim3 grid(Ll / BM, Hh, Bb);   // (32, 8, 4); x-fastest -> same-(b,h) CTAs share K/V in L2
    flash_fp16<<<grid, 128>>>(Q, K, V, Out);
}